// round 16
// baseline (speedup 1.0000x reference)
#include <cuda_runtime.h>
#include <cuda_fp16.h>
#include <cstdint>

#define CDIM 128
#define KNB 7
#define TILE_M 128
#define P1_THREADS 256
#define MAX_BN (4 * 40962)

// Inter-kernel scratch: per-(b,node) sigmoid score.
__device__ float g_s[MAX_BN];

// ---------------------------------------------------------------------------
// Dynamic SMEM layout (bytes): W (fp16, transposed, swizzled) + A (fp16 tile)
// A region doubles as fp32 staging scratch for the one-time W transpose.
// ---------------------------------------------------------------------------
#define OFF_W  0
#define OFF_A  32768
#define OFF_B1 (OFF_A + 32768)
#define OFF_V  (OFF_B1 + 512)
#define SMEM_TOTAL (OFF_V + 512)   // 66,560 B -> 2 CTAs/SM

__device__ __forceinline__ uint32_t smem_u32(const void* p) {
    uint32_t a;
    asm("{ .reg .u64 t; cvta.to.shared.u64 t, %1; cvt.u32.u64 %0, t; }" : "=r"(a) : "l"(p));
    return a;
}

// Swizzled byte offset inside a [128 rows][128 fp16] tile.
// Row = 256 B = 16 units of 16 B; unit index XORed with (row & 7) so
// ldmatrix's 8-row reads hit distinct 16B groups (conflict-free; verified R8-R14).
__device__ __forceinline__ uint32_t swz(int row, int k) {
    return (uint32_t)(row * 256 + ((((k >> 3) ^ (row & 7)) << 4) | ((k & 7) << 1)));
}

__device__ __forceinline__ void ldsm4(uint32_t r[4], uint32_t addr) {
    asm volatile("ldmatrix.sync.aligned.m8n8.x4.shared.b16 {%0,%1,%2,%3}, [%4];"
                 : "=r"(r[0]), "=r"(r[1]), "=r"(r[2]), "=r"(r[3]) : "r"(addr));
}

__device__ __forceinline__ void mma16816(float c[4], const uint32_t a[4],
                                         uint32_t b0, uint32_t b1) {
    asm volatile(
        "mma.sync.aligned.m16n8k16.row.col.f32.f16.f16.f32 "
        "{%0,%1,%2,%3}, {%4,%5,%6,%7}, {%8,%9}, {%0,%1,%2,%3};"
        : "+f"(c[0]), "+f"(c[1]), "+f"(c[2]), "+f"(c[3])
        : "r"(a[0]), "r"(a[1]), "r"(a[2]), "r"(a[3]), "r"(b0), "r"(b1));
}

__device__ __forceinline__ float tanh_a(float x) {
    float y; asm("tanh.approx.f32 %0, %1;" : "=f"(y) : "f"(x)); return y;
}

// ============================================================================
// Pass 1 (R10 verbatim — measured ~51us): HMMA, TILE_M=128, 2 CTAs/SM
// (implicit staging/MMA overlap between sibling CTAs):
//   s[row] = sigmoid( tanh(q[row]@W1 + b1) . V + bV )
// ============================================================================
__global__ __launch_bounds__(P1_THREADS, 2)
void pass1_hmma(const float* __restrict__ query, const float* __restrict__ W1,
                const float* __restrict__ b1, const float* __restrict__ Vw,
                const float* __restrict__ bV, int BN)
{
    extern __shared__ char smem[];
    const uint32_t sb = smem_u32(smem);
    const int tid = threadIdx.x, lane = tid & 31, wrp = tid >> 5;

    // ---- One-time: W1 -> transposed fp16 W_t[d][c] in two 64-row chunks,
    // using the A region as coalesced fp32 staging scratch.
    float* tmpW = (float*)(smem + OFF_A);   // 64 rows x 128 fp32 = 32 KB
    for (int half = 0; half < 2; half++) {
        for (int i = tid; i < 64 * CDIM / 4; i += P1_THREADS)
            ((float4*)tmpW)[i] = ((const float4*)(W1 + half * 64 * CDIM))[i];
        __syncthreads();
        for (int i = tid; i < CDIM * 32; i += P1_THREADS) {
            int d = i >> 5, r = (i & 31) * 2;        // local rows r, r+1
            __half2 hp = __floats2half2_rn(tmpW[(r + 0) * CDIM + d],
                                           tmpW[(r + 1) * CDIM + d]);
            *(__half2*)(smem + OFF_W + swz(d, half * 64 + r)) = hp;
        }
        __syncthreads();
    }
    if (tid < CDIM) {
        ((float*)(smem + OFF_B1))[tid] = b1[tid];
        ((float*)(smem + OFF_V))[tid]  = Vw[tid];
    }
    __syncthreads();

    const float* sB1 = (const float*)(smem + OFF_B1);
    const float* sV  = (const float*)(smem + OFF_V);
    const float bV0 = bV[0];

    // per-lane ldmatrix addressing components
    const int lrow = lane & 15;               // row within 16-row tile
    const int lkof = (lane >> 4) << 3;        // k offset (0 or 8)
    const int r0 = wrp * 16;                  // this warp's row base in tile
    const int cq = 2 * (lane & 3);            // this lane's col pair offset

    const int ntiles = (BN + TILE_M - 1) / TILE_M;

    for (int tile = blockIdx.x; tile < ntiles; tile += gridDim.x) {
        // ---- Stage A tile: q fp32 -> fp16 via LDG.128 + STS.64, swizzled
        #pragma unroll
        for (int it = 0; it < TILE_M * 32 / P1_THREADS; it++) {   // 16 iters
            int i = tid + it * P1_THREADS;
            int row = i >> 5, c4 = (i & 31) * 4;
            long grow = (long)tile * TILE_M + row;
            float4 q4 = make_float4(0.f, 0.f, 0.f, 0.f);
            if (grow < BN) q4 = *(const float4*)(query + grow * CDIM + c4);
            __half2 h01 = __floats2half2_rn(q4.x, q4.y);
            __half2 h23 = __floats2half2_rn(q4.z, q4.w);
            uint2 pk;
            pk.x = *(uint32_t*)&h01;
            pk.y = *(uint32_t*)&h23;
            *(uint2*)(smem + OFF_A + swz(row, c4)) = pk;
        }
        __syncthreads();

        // ---- Full-width accumulator, b1 folded into init.
        // acc[t][0..1] -> row lane/4,   cols t*8 + cq + {0,1}
        // acc[t][2..3] -> row lane/4+8, same cols
        float acc[16][4];
        #pragma unroll
        for (int t = 0; t < 16; t++) {
            float b0 = sB1[t * 8 + cq], b1v = sB1[t * 8 + cq + 1];
            acc[t][0] = b0; acc[t][1] = b1v;
            acc[t][2] = b0; acc[t][3] = b1v;
        }

        #pragma unroll
        for (int k0 = 0; k0 < CDIM; k0 += 16) {
            uint32_t a[4];
            ldsm4(a, sb + OFF_A + swz(r0 + lrow, k0 + lkof));
            #pragma unroll
            for (int tp = 0; tp < 8; tp++) {
                uint32_t bh[4];
                ldsm4(bh, sb + OFF_W + swz(tp * 16 + lrow, k0 + lkof));
                mma16816(acc[2 * tp],     a, bh[0], bh[2]);
                mma16816(acc[2 * tp + 1], a, bh[1], bh[3]);
            }
        }

        // ---- Epilogue: tanh . V, per-lane partials over this lane's 32 cols
        float zlo = 0.f, zhi = 0.f;
        #pragma unroll
        for (int t = 0; t < 16; t++) {
            float v0 = sV[t * 8 + cq], v1 = sV[t * 8 + cq + 1];
            zlo += tanh_a(acc[t][0]) * v0 + tanh_a(acc[t][1]) * v1;
            zhi += tanh_a(acc[t][2]) * v0 + tanh_a(acc[t][3]) * v1;
        }

        // Reduce across the 4 lanes sharing a row
        zlo += __shfl_xor_sync(0xffffffffu, zlo, 1);
        zlo += __shfl_xor_sync(0xffffffffu, zlo, 2);
        zhi += __shfl_xor_sync(0xffffffffu, zhi, 1);
        zhi += __shfl_xor_sync(0xffffffffu, zhi, 2);

        if ((lane & 3) == 0) {
            long rlo = (long)tile * TILE_M + r0 + (lane >> 2);
            long rhi = rlo + 8;
            if (rlo < BN) {
                float z = zlo + bV0;
                g_s[rlo] = __fdividef(1.0f, 1.0f + __expf(-z));
            }
            if (rhi < BN) {
                float z = zhi + bV0;
                g_s[rhi] = __fdividef(1.0f, 1.0f + __expf(-z));
            }
        }
        __syncthreads();   // all reads of A done before next tile overwrites
    }
}

// ============================================================================
// Pass 2: TWO warps per (b,n), each owning 64 channels (float2 per lane).
// Halves per-warp register state (7 float2 in flight = 14 regs) while keeping
// MLP=7, so occ(~87%) x MLP is ~2.4x the R10 scheme. Scores live one-per-lane
// (lane k owns ix_k, s_k); indices/weights distributed via shuffles.
// ============================================================================
__global__ __launch_bounds__(256, 7)
void pass2_kernel(const float* __restrict__ values, const int* __restrict__ neigh,
                  float* __restrict__ ctx, float* __restrict__ score,
                  int BN, int N)
{
    const int gw = blockIdx.x * 4 + (threadIdx.x >> 6);
    if (gw >= BN) return;
    const int lane = threadIdx.x & 31;
    const int half = (threadIdx.x >> 5) & 1;   // channel half: 0 -> 0-63, 1 -> 64-127
    const int b = gw / N;
    const int n = gw - b * N;

    // Lane k (k<7) owns neighbor k's index and raw score.
    int   myix = 0;
    float mysc = 0.f;
    if (lane < KNB) {
        myix = __ldg(neigh + (long)n * KNB + lane);
        mysc = g_s[b * N + myix];
    }

    // Gather 7 value-row segments (64 ch each), addresses via index shuffles.
    // All 7 loads independent and in flight together (MLP=7).
    const float* vb = values + (long)b * N * CDIM + half * 64 + 2 * lane;
    float2 v[KNB];
    #pragma unroll
    for (int k = 0; k < KNB; k++) {
        int ixk = __shfl_sync(0xffffffffu, myix, k);
        v[k] = *(const float2*)(vb + (long)ixk * CDIM);
    }

    // Distribute scores, form sum.
    float wk[KNB];
    float sum = 0.f;
    #pragma unroll
    for (int k = 0; k < KNB; k++) {
        wk[k] = __shfl_sync(0xffffffffu, mysc, k);
        sum += wk[k];
    }
    float inv = __fdividef(1.0f, sum);

    // score output is the raw sigmoid (pre-normalization), per reference.
    if (half == 0 && lane < KNB) score[(long)gw * KNB + lane] = mysc;

    float2 a = make_float2(0.f, 0.f);
    #pragma unroll
    for (int k = 0; k < KNB; k++) {
        float w = wk[k] * inv;
        a.x += w * v[k].x;
        a.y += w * v[k].y;
    }
    *(float2*)(ctx + (long)gw * CDIM + half * 64 + 2 * lane) = a;
}

// ============================================================================
// Launch
// ============================================================================
extern "C" void kernel_launch(void* const* d_in, const int* in_sizes, int n_in,
                              void* d_out, int out_size)
{
    const float* query  = (const float*)d_in[0];
    const float* values = (const float*)d_in[1];
    const int*   neigh  = (const int*)d_in[2];
    const float* W1     = (const float*)d_in[3];
    const float* b1     = (const float*)d_in[4];
    const float* Vw     = (const float*)d_in[5];
    const float* bV     = (const float*)d_in[6];

    const int BN = in_sizes[0] / CDIM;   // B*N
    const int N  = in_sizes[2] / KNB;    // nodes

    float* ctx   = (float*)d_out;
    float* score = (float*)d_out + (size_t)BN * CDIM;

    int nsm = 148;
    cudaDeviceGetAttribute(&nsm, cudaDevAttrMultiProcessorCount, 0);

    cudaFuncSetAttribute(pass1_hmma, cudaFuncAttributeMaxDynamicSharedMemorySize, SMEM_TOTAL);
    pass1_hmma<<<2 * nsm, P1_THREADS, SMEM_TOTAL>>>(query, W1, b1, Vw, bV, BN);

    int p2_blocks = (BN + 3) / 4;
    pass2_kernel<<<p2_blocks, 256>>>(values, neigh, ctx, score, BN, N);
}

// round 17
// speedup vs baseline: 1.1027x; 1.1027x over previous
#include <cuda_runtime.h>
#include <cuda_fp16.h>
#include <cstdint>

#define CDIM 128
#define KNB 7
#define TILE_M 128
#define P1_THREADS 256
#define MAX_BN (4 * 40962)

// Inter-kernel scratch: per-(b,node) sigmoid score.
__device__ float g_s[MAX_BN];

// ---------------------------------------------------------------------------
// Dynamic SMEM layout (bytes): W (fp16, transposed, swizzled) + A (fp16 tile)
// A region doubles as fp32 staging scratch for the one-time W transpose.
// ---------------------------------------------------------------------------
#define OFF_W  0
#define OFF_A  32768
#define OFF_B1 (OFF_A + 32768)
#define OFF_V  (OFF_B1 + 512)
#define SMEM_TOTAL (OFF_V + 512)   // 66,560 B -> 2 CTAs/SM

__device__ __forceinline__ uint32_t smem_u32(const void* p) {
    uint32_t a;
    asm("{ .reg .u64 t; cvta.to.shared.u64 t, %1; cvt.u32.u64 %0, t; }" : "=r"(a) : "l"(p));
    return a;
}

// Swizzled byte offset inside a [128 rows][128 fp16] tile.
// Row = 256 B = 16 units of 16 B; unit index XORed with (row & 7) so
// ldmatrix's 8-row reads hit distinct 16B groups (conflict-free; verified R8-R16).
__device__ __forceinline__ uint32_t swz(int row, int k) {
    return (uint32_t)(row * 256 + ((((k >> 3) ^ (row & 7)) << 4) | ((k & 7) << 1)));
}

__device__ __forceinline__ void ldsm4(uint32_t r[4], uint32_t addr) {
    asm volatile("ldmatrix.sync.aligned.m8n8.x4.shared.b16 {%0,%1,%2,%3}, [%4];"
                 : "=r"(r[0]), "=r"(r[1]), "=r"(r[2]), "=r"(r[3]) : "r"(addr));
}

__device__ __forceinline__ void mma16816(float c[4], const uint32_t a[4],
                                         uint32_t b0, uint32_t b1) {
    asm volatile(
        "mma.sync.aligned.m16n8k16.row.col.f32.f16.f16.f32 "
        "{%0,%1,%2,%3}, {%4,%5,%6,%7}, {%8,%9}, {%0,%1,%2,%3};"
        : "+f"(c[0]), "+f"(c[1]), "+f"(c[2]), "+f"(c[3])
        : "r"(a[0]), "r"(a[1]), "r"(a[2]), "r"(a[3]), "r"(b0), "r"(b1));
}

__device__ __forceinline__ float tanh_a(float x) {
    float y; asm("tanh.approx.f32 %0, %1;" : "=f"(y) : "f"(x)); return y;
}

// ============================================================================
// Pass 1 (R10 structure — best measured ~51us): HMMA, TILE_M=128, 2 CTAs/SM
// (implicit staging/MMA overlap between sibling CTAs):
//   s[row] = sigmoid( tanh(q[row]@W1 + b1) . V + bV )
// Staging uses clamped row index (no branch / zero-fill): OOB rows load row
// BN-1 harmlessly; their results are discarded at the store.
// ============================================================================
__global__ __launch_bounds__(P1_THREADS, 2)
void pass1_hmma(const float* __restrict__ query, const float* __restrict__ W1,
                const float* __restrict__ b1, const float* __restrict__ Vw,
                const float* __restrict__ bV, int BN)
{
    extern __shared__ char smem[];
    const uint32_t sb = smem_u32(smem);
    const int tid = threadIdx.x, lane = tid & 31, wrp = tid >> 5;

    // ---- One-time: W1 -> transposed fp16 W_t[d][c] in two 64-row chunks,
    // using the A region as coalesced fp32 staging scratch.
    float* tmpW = (float*)(smem + OFF_A);   // 64 rows x 128 fp32 = 32 KB
    for (int half = 0; half < 2; half++) {
        for (int i = tid; i < 64 * CDIM / 4; i += P1_THREADS)
            ((float4*)tmpW)[i] = ((const float4*)(W1 + half * 64 * CDIM))[i];
        __syncthreads();
        for (int i = tid; i < CDIM * 32; i += P1_THREADS) {
            int d = i >> 5, r = (i & 31) * 2;        // local rows r, r+1
            __half2 hp = __floats2half2_rn(tmpW[(r + 0) * CDIM + d],
                                           tmpW[(r + 1) * CDIM + d]);
            *(__half2*)(smem + OFF_W + swz(d, half * 64 + r)) = hp;
        }
        __syncthreads();
    }
    if (tid < CDIM) {
        ((float*)(smem + OFF_B1))[tid] = b1[tid];
        ((float*)(smem + OFF_V))[tid]  = Vw[tid];
    }
    __syncthreads();

    const float* sB1 = (const float*)(smem + OFF_B1);
    const float* sV  = (const float*)(smem + OFF_V);
    const float bV0 = bV[0];

    // per-lane ldmatrix addressing components
    const int lrow = lane & 15;               // row within 16-row tile
    const int lkof = (lane >> 4) << 3;        // k offset (0 or 8)
    const int r0 = wrp * 16;                  // this warp's row base in tile
    const int cq = 2 * (lane & 3);            // this lane's col pair offset

    const int ntiles = (BN + TILE_M - 1) / TILE_M;

    for (int tile = blockIdx.x; tile < ntiles; tile += gridDim.x) {
        // ---- Stage A tile: q fp32 -> fp16 via LDG.128 + STS.64, swizzled.
        // Row clamped to BN-1 (branch-free; OOB results never stored).
        #pragma unroll
        for (int it = 0; it < TILE_M * 32 / P1_THREADS; it++) {   // 16 iters
            int i = tid + it * P1_THREADS;
            int row = i >> 5, c4 = (i & 31) * 4;
            long grow = (long)tile * TILE_M + row;
            if (grow >= BN) grow = BN - 1;
            float4 q4 = *(const float4*)(query + grow * CDIM + c4);
            __half2 h01 = __floats2half2_rn(q4.x, q4.y);
            __half2 h23 = __floats2half2_rn(q4.z, q4.w);
            uint2 pk;
            pk.x = *(uint32_t*)&h01;
            pk.y = *(uint32_t*)&h23;
            *(uint2*)(smem + OFF_A + swz(row, c4)) = pk;
        }
        __syncthreads();

        // ---- Full-width accumulator, b1 folded into init.
        // acc[t][0..1] -> row lane/4,   cols t*8 + cq + {0,1}
        // acc[t][2..3] -> row lane/4+8, same cols
        float acc[16][4];
        #pragma unroll
        for (int t = 0; t < 16; t++) {
            float b0 = sB1[t * 8 + cq], b1v = sB1[t * 8 + cq + 1];
            acc[t][0] = b0; acc[t][1] = b1v;
            acc[t][2] = b0; acc[t][3] = b1v;
        }

        #pragma unroll
        for (int k0 = 0; k0 < CDIM; k0 += 16) {
            uint32_t a[4];
            ldsm4(a, sb + OFF_A + swz(r0 + lrow, k0 + lkof));
            #pragma unroll
            for (int tp = 0; tp < 8; tp++) {
                uint32_t bh[4];
                ldsm4(bh, sb + OFF_W + swz(tp * 16 + lrow, k0 + lkof));
                mma16816(acc[2 * tp],     a, bh[0], bh[2]);
                mma16816(acc[2 * tp + 1], a, bh[1], bh[3]);
            }
        }

        // ---- Epilogue: tanh . V, per-lane partials over this lane's 32 cols
        float zlo = 0.f, zhi = 0.f;
        #pragma unroll
        for (int t = 0; t < 16; t++) {
            float v0 = sV[t * 8 + cq], v1 = sV[t * 8 + cq + 1];
            zlo += tanh_a(acc[t][0]) * v0 + tanh_a(acc[t][1]) * v1;
            zhi += tanh_a(acc[t][2]) * v0 + tanh_a(acc[t][3]) * v1;
        }

        // Reduce across the 4 lanes sharing a row
        zlo += __shfl_xor_sync(0xffffffffu, zlo, 1);
        zlo += __shfl_xor_sync(0xffffffffu, zlo, 2);
        zhi += __shfl_xor_sync(0xffffffffu, zhi, 1);
        zhi += __shfl_xor_sync(0xffffffffu, zhi, 2);

        if ((lane & 3) == 0) {
            long rlo = (long)tile * TILE_M + r0 + (lane >> 2);
            long rhi = rlo + 8;
            if (rlo < BN) {
                float z = zlo + bV0;
                g_s[rlo] = __fdividef(1.0f, 1.0f + __expf(-z));
            }
            if (rhi < BN) {
                float z = zhi + bV0;
                g_s[rhi] = __fdividef(1.0f, 1.0f + __expf(-z));
            }
        }
        __syncthreads();   // all reads of A done before next tile overwrites
    }
}

// ============================================================================
// Pass 2 (R14 structure — best measured 52.3us): one warp per (b,n); fp32
// values gather, chunked 4+3 value loads (regs ~40 -> 6 blocks/SM).
// Lane l owns channels 4l..4l+3.
// ============================================================================
__global__ __launch_bounds__(256, 6)
void pass2_kernel(const float* __restrict__ values, const int* __restrict__ neigh,
                  float* __restrict__ ctx, float* __restrict__ score,
                  int BN, int N)
{
    int gw = blockIdx.x * 8 + (threadIdx.x >> 5);
    if (gw >= BN) return;
    const int lane = threadIdx.x & 31;
    const int b = gw / N;
    const int n = gw - b * N;

    const int* nb = neigh + (long)n * KNB;
    int ix[KNB];
    #pragma unroll
    for (int k = 0; k < KNB; k++) ix[k] = __ldg(nb + k);

    const float* vb = values + (long)b * N * CDIM;

    // Chunk 1: first 4 value rows in flight
    float4 t0 = *(const float4*)(vb + (long)ix[0] * CDIM + 4 * lane);
    float4 t1 = *(const float4*)(vb + (long)ix[1] * CDIM + 4 * lane);
    float4 t2 = *(const float4*)(vb + (long)ix[2] * CDIM + 4 * lane);
    float4 t3 = *(const float4*)(vb + (long)ix[3] * CDIM + 4 * lane);

    float sk[KNB];
    #pragma unroll
    for (int k = 0; k < KNB; k++) sk[k] = g_s[b * N + ix[k]];

    float sum = 0.f;
    #pragma unroll
    for (int k = 0; k < KNB; k++) sum += sk[k];
    float inv = __fdividef(1.0f, sum);

    // score output is the raw sigmoid (pre-normalization), per reference.
    if (lane < KNB) score[(long)gw * KNB + lane] = sk[lane];

    float4 a;
    {
        float w = sk[0] * inv;
        a.x = w * t0.x; a.y = w * t0.y; a.z = w * t0.z; a.w = w * t0.w;
    }
    {
        float w = sk[1] * inv;
        a.x += w * t1.x; a.y += w * t1.y; a.z += w * t1.z; a.w += w * t1.w;
    }
    // Chunk 2: last 3 rows (issued as chunk-1 registers retire)
    float4 t4 = *(const float4*)(vb + (long)ix[4] * CDIM + 4 * lane);
    float4 t5 = *(const float4*)(vb + (long)ix[5] * CDIM + 4 * lane);
    float4 t6 = *(const float4*)(vb + (long)ix[6] * CDIM + 4 * lane);
    {
        float w = sk[2] * inv;
        a.x += w * t2.x; a.y += w * t2.y; a.z += w * t2.z; a.w += w * t2.w;
    }
    {
        float w = sk[3] * inv;
        a.x += w * t3.x; a.y += w * t3.y; a.z += w * t3.z; a.w += w * t3.w;
    }
    {
        float w = sk[4] * inv;
        a.x += w * t4.x; a.y += w * t4.y; a.z += w * t4.z; a.w += w * t4.w;
    }
    {
        float w = sk[5] * inv;
        a.x += w * t5.x; a.y += w * t5.y; a.z += w * t5.z; a.w += w * t5.w;
    }
    {
        float w = sk[6] * inv;
        a.x += w * t6.x; a.y += w * t6.y; a.z += w * t6.z; a.w += w * t6.w;
    }
    *(float4*)(ctx + (long)gw * CDIM + 4 * lane) = a;
}

// ============================================================================
// Launch
// ============================================================================
extern "C" void kernel_launch(void* const* d_in, const int* in_sizes, int n_in,
                              void* d_out, int out_size)
{
    const float* query  = (const float*)d_in[0];
    const float* values = (const float*)d_in[1];
    const int*   neigh  = (const int*)d_in[2];
    const float* W1     = (const float*)d_in[3];
    const float* b1     = (const float*)d_in[4];
    const float* Vw     = (const float*)d_in[5];
    const float* bV     = (const float*)d_in[6];

    const int BN = in_sizes[0] / CDIM;   // B*N
    const int N  = in_sizes[2] / KNB;    // nodes

    float* ctx   = (float*)d_out;
    float* score = (float*)d_out + (size_t)BN * CDIM;

    int nsm = 148;
    cudaDeviceGetAttribute(&nsm, cudaDevAttrMultiProcessorCount, 0);

    cudaFuncSetAttribute(pass1_hmma, cudaFuncAttributeMaxDynamicSharedMemorySize, SMEM_TOTAL);
    pass1_hmma<<<2 * nsm, P1_THREADS, SMEM_TOTAL>>>(query, W1, b1, Vw, bV, BN);

    int p2_blocks = (BN + 7) / 8;
    pass2_kernel<<<p2_blocks, 256>>>(values, neigh, ctx, score, BN, N);
}